// round 1
// baseline (speedup 1.0000x reference)
#include <cuda_runtime.h>

#define N_TOK 8192
#define DKC   256
#define DVC   256

// Scratch for projected Q (pre-scaled by 1/sqrt(dk)), K, V.
__device__ float g_Q[N_TOK * DKC];
__device__ float g_K[N_TOK * DKC];
__device__ float g_V[N_TOK * DVC];

// ---------------------------------------------------------------------------
// Projection: out = (x @ W^T + b) * scale     (torch Linear semantics)
// x: [8192, 256], W: [256, 256] row-major (out_features x in_features)
// ---------------------------------------------------------------------------
#define PBM 64
#define PBN 64
#define PBK 16

__global__ void proj_kernel(const float* __restrict__ x,
                            const float* __restrict__ W,
                            const float* __restrict__ b,
                            int which, float scale) {
    float* out = (which == 0) ? g_Q : (which == 1) ? g_K : g_V;

    __shared__ float As[PBK][PBM];   // transposed A tile
    __shared__ float Bs[PBK][PBN];   // transposed B tile

    const int tid = threadIdx.x;          // 256 threads
    const int tx  = tid & 15;
    const int ty  = tid >> 4;
    const int m0  = blockIdx.y * PBM;
    const int n0  = blockIdx.x * PBN;

    const int lr = tid >> 2;              // 0..63: tile row to stage
    const int lk = (tid & 3) << 2;        // 0,4,8,12: k offset

    float acc[4][4] = {};

    for (int k0 = 0; k0 < DKC; k0 += PBK) {
        float4 av = *(const float4*)&x[(m0 + lr) * DKC + k0 + lk];
        float4 bv = *(const float4*)&W[(n0 + lr) * DKC + k0 + lk];
        __syncthreads();   // protect previous iteration's tile reads
        As[lk + 0][lr] = av.x; As[lk + 1][lr] = av.y;
        As[lk + 2][lr] = av.z; As[lk + 3][lr] = av.w;
        Bs[lk + 0][lr] = bv.x; Bs[lk + 1][lr] = bv.y;
        Bs[lk + 2][lr] = bv.z; Bs[lk + 3][lr] = bv.w;
        __syncthreads();
#pragma unroll
        for (int kk = 0; kk < PBK; kk++) {
            float4 a4 = *(const float4*)&As[kk][ty * 4];
            float4 b4 = *(const float4*)&Bs[kk][tx * 4];
            float aa[4] = {a4.x, a4.y, a4.z, a4.w};
            float bb[4] = {b4.x, b4.y, b4.z, b4.w};
#pragma unroll
            for (int i = 0; i < 4; i++)
#pragma unroll
                for (int j = 0; j < 4; j++)
                    acc[i][j] += aa[i] * bb[j];
        }
    }

#pragma unroll
    for (int i = 0; i < 4; i++) {
        const int row = m0 + ty * 4 + i;
#pragma unroll
        for (int j = 0; j < 4; j++) {
            const int col = n0 + tx * 4 + j;
            out[row * DKC + col] = (acc[i][j] + b[col]) * scale;
        }
    }
}

// ---------------------------------------------------------------------------
// Flash attention (non-causal, full N x N), fp32.
// One CTA = BM=32 query rows; loop over key tiles of BN=64.
// Smem rows padded to KLD=260 floats: row stride = 4 mod 32 banks, so
// warp-wide float4 loads with lane-stride-1 rows hit the 4-cycle crossbar
// floor (perfectly balanced banks).
// ---------------------------------------------------------------------------
#define BM  32
#define BN  64
#define KLD 260
#define PLD 65

#define FLASH_SMEM_FLOATS ((BM + BN + BN) * KLD + BM * PLD + 3 * BM)
#define FLASH_SMEM_BYTES  (FLASH_SMEM_FLOATS * 4)

__global__ __launch_bounds__(256, 1)
void flash_kernel(float* __restrict__ out) {
    extern __shared__ float sm[];
    float* Qs   = sm;                       // [BM][KLD]
    float* Ks   = Qs + BM * KLD;            // [BN][KLD]
    float* Vs   = Ks + BN * KLD;            // [BN][KLD]
    float* Ps   = Vs + BN * KLD;            // [BM][PLD]
    float* sm_m = Ps + BM * PLD;            // [BM]
    float* sm_l = sm_m + BM;                // [BM]
    float* sm_a = sm_l + BM;                // [BM]

    const int tid  = threadIdx.x;           // 256
    const int m0   = blockIdx.x * BM;
    const int lane = tid & 31;
    const int wy   = tid >> 5;              // warp id 0..7 -> S rows wy*4..+3

    // PV / output mapping: row = tid/8, cols = cg + u*32 (u=0..7)
    const int orow = tid >> 3;
    const int cg   = (tid & 7) << 2;

    // Load Q tile (32 x 256 = 2048 float4)
    for (int t = tid; t < BM * 64; t += 256) {
        const int r = t >> 6, c4 = (t & 63) << 2;
        *(float4*)&Qs[r * KLD + c4] = *(const float4*)&g_Q[(m0 + r) * DKC + c4];
    }
    if (tid < BM) { sm_m[tid] = -1e30f; sm_l[tid] = 0.0f; }

    float o[8][4] = {};

    for (int j0 = 0; j0 < N_TOK; j0 += BN) {
        __syncthreads();   // Ks/Vs free (prev PV done); also orders Q/m/l init
        for (int t = tid; t < BN * 64; t += 256) {
            const int r = t >> 6, c4 = (t & 63) << 2;
            *(float4*)&Ks[r * KLD + c4] = *(const float4*)&g_K[(j0 + r) * DKC + c4];
            *(float4*)&Vs[r * KLD + c4] = *(const float4*)&g_V[(j0 + r) * DVC + c4];
        }
        __syncthreads();

        // ---- S = Qs @ Ks^T : this warp computes rows wy*4..+3, cols lane, lane+32
        float s[4][2] = {};
#pragma unroll 4
        for (int d = 0; d < DKC; d += 4) {
            const float4 k0v = *(const float4*)&Ks[lane * KLD + d];
            const float4 k1v = *(const float4*)&Ks[(lane + 32) * KLD + d];
#pragma unroll
            for (int i = 0; i < 4; i++) {
                const float4 q = *(const float4*)&Qs[(wy * 4 + i) * KLD + d];
                s[i][0] += q.x * k0v.x + q.y * k0v.y + q.z * k0v.z + q.w * k0v.w;
                s[i][1] += q.x * k1v.x + q.y * k1v.y + q.z * k1v.z + q.w * k1v.w;
            }
        }

        // ---- online softmax per row (warp-local: each warp owns 4 full rows)
#pragma unroll
        for (int i = 0; i < 4; i++) {
            const int r = wy * 4 + i;
            float mt = fmaxf(s[i][0], s[i][1]);
#pragma unroll
            for (int off = 16; off; off >>= 1)
                mt = fmaxf(mt, __shfl_xor_sync(0xffffffffu, mt, off));
            const float mold = sm_m[r];
            const float mnew = fmaxf(mold, mt);
            const float p0 = __expf(s[i][0] - mnew);
            const float p1 = __expf(s[i][1] - mnew);
            float rs = p0 + p1;
#pragma unroll
            for (int off = 16; off; off >>= 1)
                rs += __shfl_xor_sync(0xffffffffu, rs, off);
            const float alpha = __expf(mold - mnew);
            if (lane == 0) {
                sm_m[r] = mnew;
                sm_l[r] = sm_l[r] * alpha + rs;
                sm_a[r] = alpha;
            }
            Ps[r * PLD + lane]      = p0;
            Ps[r * PLD + lane + 32] = p1;
        }
        __syncthreads();

        // ---- O = O*alpha + Ps @ Vs
        const float alpha = sm_a[orow];
#pragma unroll
        for (int u = 0; u < 8; u++)
#pragma unroll
            for (int w = 0; w < 4; w++) o[u][w] *= alpha;

#pragma unroll 8
        for (int jj = 0; jj < BN; jj++) {
            const float p = Ps[orow * PLD + jj];
#pragma unroll
            for (int u = 0; u < 8; u++) {
                const float4 v = *(const float4*)&Vs[jj * KLD + cg + u * 32];
                o[u][0] += p * v.x; o[u][1] += p * v.y;
                o[u][2] += p * v.z; o[u][3] += p * v.w;
            }
        }
    }

    // ---- epilogue: divide by softmax denominator, store
    const float inv = 1.0f / sm_l[orow];
#pragma unroll
    for (int u = 0; u < 8; u++) {
        float4 v = make_float4(o[u][0] * inv, o[u][1] * inv,
                               o[u][2] * inv, o[u][3] * inv);
        *(float4*)&out[(m0 + orow) * DVC + cg + u * 32] = v;
    }
}

// ---------------------------------------------------------------------------
// Entry point
// ---------------------------------------------------------------------------
extern "C" void kernel_launch(void* const* d_in, const int* in_sizes, int n_in,
                              void* d_out, int out_size) {
    const float* q  = (const float*)d_in[0];
    const float* k  = (const float*)d_in[1];
    const float* v  = (const float*)d_in[2];
    const float* Wq = (const float*)d_in[3];
    const float* bq = (const float*)d_in[4];
    const float* Wk = (const float*)d_in[5];
    const float* bk = (const float*)d_in[6];
    const float* Wv = (const float*)d_in[7];
    const float* bv = (const float*)d_in[8];
    float* out = (float*)d_out;

    cudaFuncSetAttribute(flash_kernel,
                         cudaFuncAttributeMaxDynamicSharedMemorySize,
                         FLASH_SMEM_BYTES);

    dim3 gridP(DKC / PBN, N_TOK / PBM);   // (4, 128)
    // Q pre-scaled by 1/sqrt(256) = 1/16 (folds softmax scale into projection)
    proj_kernel<<<gridP, 256>>>(q, Wq, bq, 0, 0.0625f);
    proj_kernel<<<gridP, 256>>>(k, Wk, bk, 1, 1.0f);
    proj_kernel<<<gridP, 256>>>(v, Wv, bv, 2, 1.0f);

    flash_kernel<<<N_TOK / BM, 256, FLASH_SMEM_BYTES>>>(out);
}

// round 4
// speedup vs baseline: 4.8079x; 4.8079x over previous
#include <cuda_runtime.h>
#include <cstdint>

#define N_TOK 8192
#define DKC   256
#define DVC   256

// Projected Q (pre-scaled by 1/sqrt(dk)), K, V — values pre-rounded to tf32.
__device__ float g_Q[N_TOK * DKC];
__device__ float g_K[N_TOK * DKC];
__device__ float g_V[N_TOK * DVC];

__device__ __forceinline__ uint32_t f2tf32(float x) {
    uint32_t u;
    asm("cvt.rna.tf32.f32 %0, %1;" : "=r"(u) : "f"(x));
    return u;
}

__device__ __forceinline__ void mma_tf32(float* d,
                                         uint32_t a0, uint32_t a1, uint32_t a2, uint32_t a3,
                                         uint32_t b0, uint32_t b1) {
    asm volatile("mma.sync.aligned.m16n8k8.row.col.f32.tf32.tf32.f32 "
                 "{%0,%1,%2,%3}, {%4,%5,%6,%7}, {%8,%9}, {%0,%1,%2,%3};"
                 : "+f"(d[0]), "+f"(d[1]), "+f"(d[2]), "+f"(d[3])
                 : "r"(a0), "r"(a1), "r"(a2), "r"(a3), "r"(b0), "r"(b1));
}

// ---------------------------------------------------------------------------
// Projection: out = (x @ W^T + b) * scale, rounded to tf32.
// x: [8192, 256], W: [256, 256] row-major (out_features x in_features)
// ---------------------------------------------------------------------------
#define PBM 64
#define PBN 64
#define PBK 16

__global__ void proj_kernel(const float* __restrict__ x,
                            const float* __restrict__ W,
                            const float* __restrict__ b,
                            int which, float scale) {
    float* out = (which == 0) ? g_Q : (which == 1) ? g_K : g_V;

    __shared__ float As[PBK][PBM];
    __shared__ float Bs[PBK][PBN];

    const int tid = threadIdx.x;          // 256 threads
    const int tx  = tid & 15;
    const int ty  = tid >> 4;
    const int m0  = blockIdx.y * PBM;
    const int n0  = blockIdx.x * PBN;

    const int lr = tid >> 2;
    const int lk = (tid & 3) << 2;

    float acc[4][4] = {};

    for (int k0 = 0; k0 < DKC; k0 += PBK) {
        float4 av = *(const float4*)&x[(m0 + lr) * DKC + k0 + lk];
        float4 bv = *(const float4*)&W[(n0 + lr) * DKC + k0 + lk];
        __syncthreads();
        As[lk + 0][lr] = av.x; As[lk + 1][lr] = av.y;
        As[lk + 2][lr] = av.z; As[lk + 3][lr] = av.w;
        Bs[lk + 0][lr] = bv.x; Bs[lk + 1][lr] = bv.y;
        Bs[lk + 2][lr] = bv.z; Bs[lk + 3][lr] = bv.w;
        __syncthreads();
#pragma unroll
        for (int kk = 0; kk < PBK; kk++) {
            float4 a4 = *(const float4*)&As[kk][ty * 4];
            float4 b4 = *(const float4*)&Bs[kk][tx * 4];
            float aa[4] = {a4.x, a4.y, a4.z, a4.w};
            float bb[4] = {b4.x, b4.y, b4.z, b4.w};
#pragma unroll
            for (int i = 0; i < 4; i++)
#pragma unroll
                for (int j = 0; j < 4; j++)
                    acc[i][j] += aa[i] * bb[j];
        }
    }

#pragma unroll
    for (int i = 0; i < 4; i++) {
        const int row = m0 + ty * 4 + i;
#pragma unroll
        for (int j = 0; j < 4; j++) {
            const int col = n0 + tx * 4 + j;
            out[row * DKC + col] =
                __uint_as_float(f2tf32((acc[i][j] + b[col]) * scale));
        }
    }
}

// ---------------------------------------------------------------------------
// Flash attention with tf32 mma.sync (m16n8k8).
// BM=64 query rows / CTA (grid 128 = one wave), BN=64 key tile.
// 8 warps: wm = wid&3 (16-row slab), wn = wid>>2 (S: 32 cols, PV: 128 cols).
// Smem strides: Q/K 260 (==4 mod 32), V 264 (==8 mod 32), P 68 (==4 mod 32)
// -> every fragment LDS hits 32 distinct banks.
// ---------------------------------------------------------------------------
#define BM   64
#define BN   64
#define QLD  260
#define KLD  260
#define VLD  264
#define PLD  68

#define SM_Q    0
#define SM_K    (SM_Q + BM * QLD)
#define SM_V    (SM_K + BN * KLD)
#define SM_P    (SM_V + BN * VLD)
#define SM_RMAX (SM_P + BM * PLD)
#define SM_RSUM (SM_RMAX + 2 * BM)
#define FLASH_SMEM_FLOATS (SM_RSUM + 2 * BM)
#define FLASH_SMEM_BYTES  (FLASH_SMEM_FLOATS * 4)

__global__ __launch_bounds__(256, 1)
void flash_kernel(float* __restrict__ out) {
    extern __shared__ float sm[];
    float*    rmax  = sm + SM_RMAX;
    float*    rsum  = sm + SM_RSUM;
    uint32_t* Qsu   = (uint32_t*)(sm + SM_Q);
    uint32_t* Ksu   = (uint32_t*)(sm + SM_K);
    uint32_t* Vsu   = (uint32_t*)(sm + SM_V);
    uint32_t* Psu   = (uint32_t*)(sm + SM_P);

    const int tid  = threadIdx.x;          // 256
    const int m0   = blockIdx.x * BM;
    const int lane = tid & 31;
    const int wid  = tid >> 5;
    const int grp  = lane >> 2;            // 0..7
    const int tig  = lane & 3;             // 0..3
    const int wm   = wid & 3;              // row slab
    const int wn   = wid >> 2;             // 0..1

    const int rA = wm * 16 + grp;          // this lane's output rows
    const int rB = rA + 8;

    // Stage Q tile (values already tf32-rounded in gmem)
    for (int t = tid; t < BM * 64; t += 256) {
        const int r = t >> 6, c4 = (t & 63) << 2;
        *(float4*)&sm[SM_Q + r * QLD + c4] = *(const float4*)&g_Q[(m0 + r) * DKC + c4];
    }

    float mA = -1e30f, mB = -1e30f, lA = 0.0f, lB = 0.0f;
    float oacc[16][4] = {};                // rows rA/rB, cols wn*128 + t*8 + {2tig,2tig+1}

    for (int j0 = 0; j0 < N_TOK; j0 += BN) {
        __syncthreads();                   // K/V/P buffers free
        for (int t = tid; t < BN * 64; t += 256) {
            const int r = t >> 6, c4 = (t & 63) << 2;
            *(float4*)&sm[SM_K + r * KLD + c4] = *(const float4*)&g_K[(j0 + r) * DKC + c4];
            *(float4*)&sm[SM_V + r * VLD + c4] = *(const float4*)&g_V[(j0 + r) * DVC + c4];
        }
        __syncthreads();

        // ---- S = Q K^T : warp computes rows wm*16..+15, cols wn*32..+31
        float sacc[4][4] = {};
        const int aro0 = rA * QLD;
        const int aro1 = aro0 + 8 * QLD;
#pragma unroll 4
        for (int k0 = 0; k0 < DKC; k0 += 8) {
            const uint32_t a0 = Qsu[aro0 + k0 + tig];
            const uint32_t a1 = Qsu[aro1 + k0 + tig];
            const uint32_t a2 = Qsu[aro0 + k0 + tig + 4];
            const uint32_t a3 = Qsu[aro1 + k0 + tig + 4];
#pragma unroll
            for (int j = 0; j < 4; j++) {
                const int bo = (wn * 32 + j * 8 + grp) * KLD + k0 + tig;
                mma_tf32(sacc[j], a0, a1, a2, a3, Ksu[bo], Ksu[bo + 4]);
            }
        }

        // ---- online softmax: partial row max (32 cols per warp)
        float vA = -1e30f, vB = -1e30f;
#pragma unroll
        for (int j = 0; j < 4; j++) {
            vA = fmaxf(vA, fmaxf(sacc[j][0], sacc[j][1]));
            vB = fmaxf(vB, fmaxf(sacc[j][2], sacc[j][3]));
        }
        vA = fmaxf(vA, __shfl_xor_sync(0xffffffffu, vA, 1));
        vA = fmaxf(vA, __shfl_xor_sync(0xffffffffu, vA, 2));
        vB = fmaxf(vB, __shfl_xor_sync(0xffffffffu, vB, 1));
        vB = fmaxf(vB, __shfl_xor_sync(0xffffffffu, vB, 2));
        if (tig == 0) { rmax[rA * 2 + wn] = vA; rmax[rB * 2 + wn] = vB; }
        __syncthreads();

        const float mnA = fmaxf(mA, fmaxf(rmax[rA * 2], rmax[rA * 2 + 1]));
        const float mnB = fmaxf(mB, fmaxf(rmax[rB * 2], rmax[rB * 2 + 1]));

        float sA = 0.0f, sB = 0.0f;
#pragma unroll
        for (int j = 0; j < 4; j++) {
            const float p0 = __expf(sacc[j][0] - mnA);
            const float p1 = __expf(sacc[j][1] - mnA);
            const float p2 = __expf(sacc[j][2] - mnB);
            const float p3 = __expf(sacc[j][3] - mnB);
            sA += p0 + p1; sB += p2 + p3;
            const int col = wn * 32 + j * 8 + 2 * tig;
            Psu[rA * PLD + col]     = f2tf32(p0);
            Psu[rA * PLD + col + 1] = f2tf32(p1);
            Psu[rB * PLD + col]     = f2tf32(p2);
            Psu[rB * PLD + col + 1] = f2tf32(p3);
        }
        sA += __shfl_xor_sync(0xffffffffu, sA, 1);
        sA += __shfl_xor_sync(0xffffffffu, sA, 2);
        sB += __shfl_xor_sync(0xffffffffu, sB, 1);
        sB += __shfl_xor_sync(0xffffffffu, sB, 2);
        if (tig == 0) { rsum[rA * 2 + wn] = sA; rsum[rB * 2 + wn] = sB; }
        __syncthreads();

        const float alphaA = __expf(mA - mnA);
        const float alphaB = __expf(mB - mnB);
        lA = lA * alphaA + rsum[rA * 2] + rsum[rA * 2 + 1];
        lB = lB * alphaB + rsum[rB * 2] + rsum[rB * 2 + 1];
        mA = mnA; mB = mnB;

#pragma unroll
        for (int t = 0; t < 16; t++) {
            oacc[t][0] *= alphaA; oacc[t][1] *= alphaA;
            oacc[t][2] *= alphaB; oacc[t][3] *= alphaB;
        }

        // ---- O += P V : warp computes rows wm*16..+15, cols wn*128..+127
        const int pro0 = rA * PLD;
        const int pro1 = pro0 + 8 * PLD;
#pragma unroll
        for (int kk = 0; kk < BN; kk += 8) {
            const uint32_t a0 = Psu[pro0 + kk + tig];
            const uint32_t a1 = Psu[pro1 + kk + tig];
            const uint32_t a2 = Psu[pro0 + kk + tig + 4];
            const uint32_t a3 = Psu[pro1 + kk + tig + 4];
            const int vr0 = (kk + tig) * VLD;
#pragma unroll
            for (int t = 0; t < 16; t++) {
                const int col = wn * 128 + t * 8 + grp;
                mma_tf32(oacc[t], a0, a1, a2, a3,
                         Vsu[vr0 + col], Vsu[vr0 + 4 * VLD + col]);
            }
        }
    }

    // ---- epilogue
    const float invA = 1.0f / lA;
    const float invB = 1.0f / lB;
#pragma unroll
    for (int t = 0; t < 16; t++) {
        const int col = wn * 128 + t * 8 + 2 * tig;
        *(float2*)&out[(m0 + rA) * DVC + col] =
            make_float2(oacc[t][0] * invA, oacc[t][1] * invA);
        *(float2*)&out[(m0 + rB) * DVC + col] =
            make_float2(oacc[t][2] * invB, oacc[t][3] * invB);
    }
}

// ---------------------------------------------------------------------------
// Entry point
// ---------------------------------------------------------------------------
extern "C" void kernel_launch(void* const* d_in, const int* in_sizes, int n_in,
                              void* d_out, int out_size) {
    const float* q  = (const float*)d_in[0];
    const float* k  = (const float*)d_in[1];
    const float* v  = (const float*)d_in[2];
    const float* Wq = (const float*)d_in[3];
    const float* bq = (const float*)d_in[4];
    const float* Wk = (const float*)d_in[5];
    const float* bk = (const float*)d_in[6];
    const float* Wv = (const float*)d_in[7];
    const float* bv = (const float*)d_in[8];
    float* out = (float*)d_out;

    cudaFuncSetAttribute(flash_kernel,
                         cudaFuncAttributeMaxDynamicSharedMemorySize,
                         FLASH_SMEM_BYTES);

    dim3 gridP(DKC / PBN, N_TOK / PBM);   // (4, 128)
    proj_kernel<<<gridP, 256>>>(q, Wq, bq, 0, 0.0625f);  // fold 1/sqrt(dk)
    proj_kernel<<<gridP, 256>>>(k, Wk, bk, 1, 1.0f);
    proj_kernel<<<gridP, 256>>>(v, Wv, bv, 2, 1.0f);

    flash_kernel<<<N_TOK / BM, 256, FLASH_SMEM_BYTES>>>(out);
}

// round 6
// speedup vs baseline: 5.6709x; 1.1795x over previous
#include <cuda_runtime.h>
#include <cstdint>

#define N_TOK 8192
#define DKC   256
#define DVC   256

// Projected Q (pre-scaled by 1/sqrt(dk)), K, V — values pre-rounded to tf32.
__device__ float g_Q[N_TOK * DKC];
__device__ float g_K[N_TOK * DKC];
__device__ float g_V[N_TOK * DVC];

__device__ __forceinline__ uint32_t f2tf32(float x) {
    uint32_t u;
    asm("cvt.rna.tf32.f32 %0, %1;" : "=r"(u) : "f"(x));
    return u;
}

__device__ __forceinline__ void mma_tf32(float* d,
                                         uint32_t a0, uint32_t a1, uint32_t a2, uint32_t a3,
                                         uint32_t b0, uint32_t b1) {
    asm volatile("mma.sync.aligned.m16n8k8.row.col.f32.tf32.tf32.f32 "
                 "{%0,%1,%2,%3}, {%4,%5,%6,%7}, {%8,%9}, {%0,%1,%2,%3};"
                 : "+f"(d[0]), "+f"(d[1]), "+f"(d[2]), "+f"(d[3])
                 : "r"(a0), "r"(a1), "r"(a2), "r"(a3), "r"(b0), "r"(b1));
}

__device__ __forceinline__ void cpa16(uint32_t smem_addr, const void* gptr) {
    asm volatile("cp.async.cg.shared.global [%0], [%1], 16;"
                 :: "r"(smem_addr), "l"(gptr));
}
#define CPA_COMMIT()  asm volatile("cp.async.commit_group;")
#define CPA_WAIT(n)   asm volatile("cp.async.wait_group %0;" :: "n"(n))

// ---------------------------------------------------------------------------
// Projection: out = (x @ W^T + b) * scale, rounded to tf32.
// ---------------------------------------------------------------------------
#define PBM 64
#define PBN 64
#define PBK 16

__global__ void proj_kernel(const float* __restrict__ x,
                            const float* __restrict__ W,
                            const float* __restrict__ b,
                            int which, float scale) {
    float* out = (which == 0) ? g_Q : (which == 1) ? g_K : g_V;

    __shared__ float As[PBK][PBM];
    __shared__ float Bs[PBK][PBN];

    const int tid = threadIdx.x;          // 256 threads
    const int tx  = tid & 15;
    const int ty  = tid >> 4;
    const int m0  = blockIdx.y * PBM;
    const int n0  = blockIdx.x * PBN;

    const int lr = tid >> 2;
    const int lk = (tid & 3) << 2;

    float acc[4][4] = {};

    for (int k0 = 0; k0 < DKC; k0 += PBK) {
        float4 av = *(const float4*)&x[(m0 + lr) * DKC + k0 + lk];
        float4 bv = *(const float4*)&W[(n0 + lr) * DKC + k0 + lk];
        __syncthreads();
        As[lk + 0][lr] = av.x; As[lk + 1][lr] = av.y;
        As[lk + 2][lr] = av.z; As[lk + 3][lr] = av.w;
        Bs[lk + 0][lr] = bv.x; Bs[lk + 1][lr] = bv.y;
        Bs[lk + 2][lr] = bv.z; Bs[lk + 3][lr] = bv.w;
        __syncthreads();
#pragma unroll
        for (int kk = 0; kk < PBK; kk++) {
            float4 a4 = *(const float4*)&As[kk][ty * 4];
            float4 b4 = *(const float4*)&Bs[kk][tx * 4];
            float aa[4] = {a4.x, a4.y, a4.z, a4.w};
            float bb[4] = {b4.x, b4.y, b4.z, b4.w};
#pragma unroll
            for (int i = 0; i < 4; i++)
#pragma unroll
                for (int j = 0; j < 4; j++)
                    acc[i][j] += aa[i] * bb[j];
        }
    }

#pragma unroll
    for (int i = 0; i < 4; i++) {
        const int row = m0 + ty * 4 + i;
#pragma unroll
        for (int j = 0; j < 4; j++) {
            const int col = n0 + tx * 4 + j;
            out[row * DKC + col] =
                __uint_as_float(f2tf32((acc[i][j] + b[col]) * scale));
        }
    }
}

// ---------------------------------------------------------------------------
// Flash attention, tf32 mma.sync, cp.async phase-shifted pipelining:
//   tile top: wait K[t], barrier, issue V[t]   (V buffer free: prev PV done)
//   after S + rmax barrier: issue K[t+1]       (K buffer free: S done)
//   before rsum barrier: wait V[t]
// 3 barriers/tile; all global->smem latency hidden behind compute.
// ---------------------------------------------------------------------------
#define BM   64
#define BN   64
#define QLD  260
#define KLD  260
#define VLD  264
#define PLD  68
#define NTILES (N_TOK / BN)

#define SM_Q    0
#define SM_K    (SM_Q + BM * QLD)
#define SM_V    (SM_K + BN * KLD)
#define SM_P    (SM_V + BN * VLD)
#define SM_RMAX (SM_P + BM * PLD)
#define SM_RSUM (SM_RMAX + 2 * BM)
#define FLASH_SMEM_FLOATS (SM_RSUM + 2 * BM)
#define FLASH_SMEM_BYTES  (FLASH_SMEM_FLOATS * 4)

__global__ __launch_bounds__(256, 1)
void flash_kernel(float* __restrict__ out) {
    extern __shared__ float sm[];
    float*    rmax  = sm + SM_RMAX;
    float*    rsum  = sm + SM_RSUM;
    uint32_t* Qsu   = (uint32_t*)(sm + SM_Q);
    uint32_t* Ksu   = (uint32_t*)(sm + SM_K);
    uint32_t* Vsu   = (uint32_t*)(sm + SM_V);
    uint32_t* Psu   = (uint32_t*)(sm + SM_P);

    const uint32_t smb = (uint32_t)__cvta_generic_to_shared(sm);

    const int tid  = threadIdx.x;          // 256
    const int m0   = blockIdx.x * BM;
    const int lane = tid & 31;
    const int wid  = tid >> 5;
    const int grp  = lane >> 2;            // 0..7
    const int tig  = lane & 3;             // 0..3
    const int wm   = wid & 3;              // row slab
    const int wn   = wid >> 2;             // 0..1

    const int rA = wm * 16 + grp;          // this lane's output rows
    const int rB = rA + 8;

    // Per-thread staging slots (16 rows x full width per thread over the tile)
    const int sr = tid >> 6;               // 0..3: row group base (stride 4)
    const int sc = (tid & 63) << 2;        // float4 column

    // ---- prologue: Q tile + K[0] via cp.async (one group)
#pragma unroll
    for (int rr = 0; rr < 16; rr++) {
        const int r = rr * 4 + sr;
        cpa16(smb + (SM_Q + r * QLD + sc) * 4, &g_Q[(m0 + r) * DKC + sc]);
    }
#pragma unroll
    for (int rr = 0; rr < 16; rr++) {
        const int r = rr * 4 + sr;
        cpa16(smb + (SM_K + r * KLD + sc) * 4, &g_K[r * DKC + sc]);
    }
    CPA_COMMIT();

    float mA = -1e30f, mB = -1e30f, lA = 0.0f, lB = 0.0f;
    float oacc[16][4] = {};

    for (int t = 0; t < NTILES; t++) {
        const int j0  = t * BN;
        const int j0n = ((t + 1) * BN) & (N_TOK - 1);   // wraps on last tile

        // ---- K[t] (and Q on t=0) complete; make visible; V buffer is free
        CPA_WAIT(0);
        __syncthreads();                                // barrier 1

        // ---- kick off V[t] (consumed after barrier 3)
#pragma unroll
        for (int rr = 0; rr < 16; rr++) {
            const int r = rr * 4 + sr;
            cpa16(smb + (SM_V + r * VLD + sc) * 4, &g_V[(j0 + r) * DVC + sc]);
        }
        CPA_COMMIT();                                   // pending: {V[t]}

        // ---- S = Q K^T : warp rows wm*16..+15, cols wn*32..+31
        float sacc[4][4] = {};
        const int aro0 = rA * QLD;
        const int aro1 = aro0 + 8 * QLD;
#pragma unroll 4
        for (int k0 = 0; k0 < DKC; k0 += 8) {
            const uint32_t a0 = Qsu[aro0 + k0 + tig];
            const uint32_t a1 = Qsu[aro1 + k0 + tig];
            const uint32_t a2 = Qsu[aro0 + k0 + tig + 4];
            const uint32_t a3 = Qsu[aro1 + k0 + tig + 4];
#pragma unroll
            for (int j = 0; j < 4; j++) {
                const int bo = (wn * 32 + j * 8 + grp) * KLD + k0 + tig;
                mma_tf32(sacc[j], a0, a1, a2, a3, Ksu[bo], Ksu[bo + 4]);
            }
        }

        // ---- softmax p1: partial row max (32 cols per warp)
        float vA = -1e30f, vB = -1e30f;
#pragma unroll
        for (int j = 0; j < 4; j++) {
            vA = fmaxf(vA, fmaxf(sacc[j][0], sacc[j][1]));
            vB = fmaxf(vB, fmaxf(sacc[j][2], sacc[j][3]));
        }
        vA = fmaxf(vA, __shfl_xor_sync(0xffffffffu, vA, 1));
        vA = fmaxf(vA, __shfl_xor_sync(0xffffffffu, vA, 2));
        vB = fmaxf(vB, __shfl_xor_sync(0xffffffffu, vB, 1));
        vB = fmaxf(vB, __shfl_xor_sync(0xffffffffu, vB, 2));
        if (tig == 0) { rmax[rA * 2 + wn] = vA; rmax[rB * 2 + wn] = vB; }
        __syncthreads();                                // barrier 2 (all S reads done)

        // ---- kick off K[t+1] (K buffer free now; overlaps softmax p2 + PV)
#pragma unroll
        for (int rr = 0; rr < 16; rr++) {
            const int r = rr * 4 + sr;
            cpa16(smb + (SM_K + r * KLD + sc) * 4, &g_K[(j0n + r) * DKC + sc]);
        }
        CPA_COMMIT();                                   // pending: {V[t], K[t+1]}

        // ---- softmax p2
        const float mnA = fmaxf(mA, fmaxf(rmax[rA * 2], rmax[rA * 2 + 1]));
        const float mnB = fmaxf(mB, fmaxf(rmax[rB * 2], rmax[rB * 2 + 1]));

        float sA = 0.0f, sB = 0.0f;
#pragma unroll
        for (int j = 0; j < 4; j++) {
            const float p0 = __expf(sacc[j][0] - mnA);
            const float p1 = __expf(sacc[j][1] - mnA);
            const float p2 = __expf(sacc[j][2] - mnB);
            const float p3 = __expf(sacc[j][3] - mnB);
            sA += p0 + p1; sB += p2 + p3;
            const int col = wn * 32 + j * 8 + 2 * tig;
            Psu[rA * PLD + col]     = f2tf32(p0);
            Psu[rA * PLD + col + 1] = f2tf32(p1);
            Psu[rB * PLD + col]     = f2tf32(p2);
            Psu[rB * PLD + col + 1] = f2tf32(p3);
        }
        sA += __shfl_xor_sync(0xffffffffu, sA, 1);
        sA += __shfl_xor_sync(0xffffffffu, sA, 2);
        sB += __shfl_xor_sync(0xffffffffu, sB, 1);
        sB += __shfl_xor_sync(0xffffffffu, sB, 2);
        if (tig == 0) { rsum[rA * 2 + wn] = sA; rsum[rB * 2 + wn] = sB; }

        CPA_WAIT(1);                                    // V[t] done (K[t+1] in flight)
        __syncthreads();                                // barrier 3: P, rsum, V visible

        const float alphaA = __expf(mA - mnA);
        const float alphaB = __expf(mB - mnB);
        lA = lA * alphaA + rsum[rA * 2] + rsum[rA * 2 + 1];
        lB = lB * alphaB + rsum[rB * 2] + rsum[rB * 2 + 1];
        mA = mnA; mB = mnB;

#pragma unroll
        for (int tt = 0; tt < 16; tt++) {
            oacc[tt][0] *= alphaA; oacc[tt][1] *= alphaA;
            oacc[tt][2] *= alphaB; oacc[tt][3] *= alphaB;
        }

        // ---- O += P V : warp rows wm*16..+15, cols wn*128..+127
        const int pro0 = rA * PLD;
        const int pro1 = pro0 + 8 * PLD;
#pragma unroll
        for (int kk = 0; kk < BN; kk += 8) {
            const uint32_t a0 = Psu[pro0 + kk + tig];
            const uint32_t a1 = Psu[pro1 + kk + tig];
            const uint32_t a2 = Psu[pro0 + kk + tig + 4];
            const uint32_t a3 = Psu[pro1 + kk + tig + 4];
            const int vr0 = (kk + tig) * VLD;
#pragma unroll
            for (int tt = 0; tt < 16; tt++) {
                const int col = wn * 128 + tt * 8 + grp;
                mma_tf32(oacc[tt], a0, a1, a2, a3,
                         Vsu[vr0 + col], Vsu[vr0 + 4 * VLD + col]);
            }
        }
    }

    // drain the wrapped final K prefetch before smem teardown
    CPA_WAIT(0);

    // ---- epilogue
    const float invA = 1.0f / lA;
    const float invB = 1.0f / lB;
#pragma unroll
    for (int tt = 0; tt < 16; tt++) {
        const int col = wn * 128 + tt * 8 + 2 * tig;
        *(float2*)&out[(m0 + rA) * DVC + col] =
            make_float2(oacc[tt][0] * invA, oacc[tt][1] * invA);
        *(float2*)&out[(m0 + rB) * DVC + col] =
            make_float2(oacc[tt][2] * invB, oacc[tt][3] * invB);
    }
}

// ---------------------------------------------------------------------------
// Entry point
// ---------------------------------------------------------------------------
extern "C" void kernel_launch(void* const* d_in, const int* in_sizes, int n_in,
                              void* d_out, int out_size) {
    const float* q  = (const float*)d_in[0];
    const float* k  = (const float*)d_in[1];
    const float* v  = (const float*)d_in[2];
    const float* Wq = (const float*)d_in[3];
    const float* bq = (const float*)d_in[4];
    const float* Wk = (const float*)d_in[5];
    const float* bk = (const float*)d_in[6];
    const float* Wv = (const float*)d_in[7];
    const float* bv = (const float*)d_in[8];
    float* out = (float*)d_out;

    cudaFuncSetAttribute(flash_kernel,
                         cudaFuncAttributeMaxDynamicSharedMemorySize,
                         FLASH_SMEM_BYTES);

    dim3 gridP(DKC / PBN, N_TOK / PBM);   // (4, 128)
    proj_kernel<<<gridP, 256>>>(q, Wq, bq, 0, 0.0625f);  // fold 1/sqrt(dk)
    proj_kernel<<<gridP, 256>>>(k, Wk, bk, 1, 1.0f);
    proj_kernel<<<gridP, 256>>>(v, Wv, bv, 2, 1.0f);

    flash_kernel<<<N_TOK / BM, 256, FLASH_SMEM_BYTES>>>(out);
}